// round 9
// baseline (speedup 1.0000x reference)
#include <cuda_runtime.h>
#include <math.h>

#define Bz 4
#define Cz 12
#define Hh 256
#define Ww 256
#define HW 65536
#define NMASK 96
#define HALFM 48
#define SENT16 65535u
#define SENT_F 1e12f        // == fl32(1e6f*1e6f)
#define SCAN_INF (1 << 20)
#define CFAKE 10000
#define BIGU 0x0FFFFFFFu

// ---------------- scratch ----------------------------------------------------
__device__ unsigned char g_mask[NMASK * HW];
__device__ unsigned int  g_g[NMASK * HW];        // packed col dist (lo=fg, hi=bg)
__device__ float         g_e2[HALFM * HW];       // (softmax - onehot)^2 planes
__device__ int           g_hasfg[NMASK];
__device__ int           g_anyfalse[NMASK];
__device__ double        g_acc[2];               // [0]=hausdorff S, [1]=sum logp
__device__ int           g_is64;

// ---------------- K0 ---------------------------------------------------------
__global__ void k0_init(const unsigned int* __restrict__ tgt_words) {
    int t = threadIdx.x;                          // 128 threads
    __shared__ int s_nz;
    if (t == 0) s_nz = 0;
    __syncthreads();
    if (tgt_words[2 * t + 1] != 0u) atomicOr(&s_nz, 1);
    if (t < NMASK) { g_hasfg[t] = 0; g_anyfalse[t] = 0; }
    __syncthreads();
    if (t == 0) {
        g_is64 = (s_nz == 0);
        g_acc[0] = 0.0;
        g_acc[1] = 0.0;
    }
}

__device__ __forceinline__ int load_target(const void* t, int idx) {
    if (g_is64) return (int)((const long long*)t)[idx];
    return ((const int*)t)[idx];
}

// ---------------- K1: softmax -> masks + e2 planes + CE partial --------------
__global__ void k1_masks(const float* __restrict__ pred, const void* __restrict__ tgt) {
    int pix = blockIdx.x * 256 + threadIdx.x;
    int b = pix >> 16;
    int hw = pix & (HW - 1);
    const float* p = pred + (size_t)b * Cz * HW + hw;

    int t = load_target(tgt, pix);

    float v[Cz];
    float mx = -1e30f;
    float xt = 0.0f;
#pragma unroll
    for (int c = 0; c < Cz; c++) {
        v[c] = p[c * HW];
        mx = fmaxf(mx, v[c]);
        if (c == t) xt = v[c];
    }
    float s = 0.0f;
#pragma unroll
    for (int c = 0; c < Cz; c++) {
        v[c] = expf(v[c] - mx);
        s += v[c];
    }
    float inv = 1.0f / s;
#pragma unroll
    for (int c = 0; c < Cz; c++) {
        float pv = v[c] * inv;
        g_mask[(size_t)(b * Cz + c) * HW + hw] = (unsigned char)(pv > 0.5f);
        g_mask[(size_t)(HALFM + b * Cz + c) * HW + hw] = (unsigned char)(c == t);
        float e = pv - ((c == t) ? 1.0f : 0.0f);
        g_e2[(size_t)(b * Cz + c) * HW + hw] = e * e;
    }

    float logp = xt - mx - logf(s);

    __shared__ float sred[256];
    sred[threadIdx.x] = logp;
    __syncthreads();
    for (int st = 128; st > 0; st >>= 1) {
        if (threadIdx.x < st) sred[threadIdx.x] += sred[threadIdx.x + st];
        __syncthreads();
    }
    if (threadIdx.x == 0) atomicAdd(&g_acc[1], (double)sred[0]);
}

// ---------------- K2: segmented column EDT (exact) ---------------------------
__global__ void __launch_bounds__(256) k2_cols() {
    __shared__ unsigned short sfwd[Hh][64];
    __shared__ unsigned short ssum[2][4][64];

    int tid = threadIdx.x;
    int col = tid & 63;
    int seg = tid >> 6;
    int m = blockIdx.x;
    int w = blockIdx.y * 64 + col;
    const unsigned char* msk = g_mask + (size_t)m * HW + w;

    int c1 = 255, c2 = 255;
    int ff1 = 255, ff2 = 255;
    int any = 0, anyf = 0;
#pragma unroll 8
    for (int i = 0; i < 64; i++) {
        int mv = msk[(seg * 64 + i) * Ww];
        any |= mv;
        anyf |= (mv ^ 1);
        c1 = mv ? min(c1 + 1, 255) : 0;
        c2 = mv ? 0 : min(c2 + 1, 255);
        if (!mv && ff1 == 255) ff1 = i;
        if (mv && ff2 == 255) ff2 = i;
        sfwd[seg * 64 + i][col] = (unsigned short)(c1 | (c2 << 8));
    }
    ssum[0][seg][col] = (unsigned short)(c1 | (c2 << 8));
    ssum[1][seg][col] = (unsigned short)(ff1 | (ff2 << 8));

    int anyb = __syncthreads_or(any);
    if (tid == 0 && anyb) atomicOr(&g_hasfg[m], 1);
    int anyfb = __syncthreads_or(anyf);
    if (tid == 0 && anyfb) atomicOr(&g_anyfalse[m], 1);

    int af1 = 0, af2 = 0;
#pragma unroll
    for (int s = 0; s < 4; s++) {
        unsigned int fp = ssum[1][s][col];
        af1 |= ((fp & 255u) != 255u);
        af2 |= (((fp >> 8) & 255u) != 255u);
    }
    int cin1 = CFAKE, cin2 = CFAKE;
    for (int s = 0; s < seg; s++) {
        unsigned int sp = ssum[0][s][col];
        int s1 = sp & 255, s2 = (sp >> 8) & 255;
        cin1 = min((s1 == 255) ? CFAKE : s1, cin1 + 64);
        cin2 = min((s2 == 255) ? CFAKE : s2, cin2 + 64);
    }
    int bin1 = CFAKE, bin2 = CFAKE;
    for (int s = 3; s > seg; s--) {
        unsigned int fp = ssum[1][s][col];
        int f1 = fp & 255, f2 = (fp >> 8) & 255;
        bin1 = min((f1 == 255) ? CFAKE : f1, bin1 + 64);
        bin2 = min((f2 == 255) ? CFAKE : f2, bin2 + 64);
    }

    unsigned int* gout = g_g + (size_t)m * HW + w;
    int b1 = bin1, b2 = bin2;
#pragma unroll 8
    for (int i = 63; i >= 0; i--) {
        unsigned int fw = sfwd[seg * 64 + i][col];
        int f1 = fw & 255, f2 = (fw >> 8) & 255;
        b1 = (f1 == 0) ? 0 : b1 + 1;
        b2 = (f2 == 0) ? 0 : b2 + 1;
        int fa1 = min(f1, cin1 + i + 1);
        int fa2 = min(f2, cin2 + i + 1);
        int g1 = min(fa1, b1);
        int g2v = min(fa2, b2);
        unsigned int o1 = af1 ? (unsigned int)g1 : SENT16;
        unsigned int o2 = af2 ? (unsigned int)g2v : SENT16;
        gout[(seg * 64 + i) * Ww] = o1 | (o2 << 16);
    }
}

// ---------------- K3: u16-packed 2-row exact window scan -> loss accumulate --
// Block: 8 warps = 4 row-pairs x 2 polarities; block covers 8 rows of mask m.
// pol1 warp passes d2 via smem; pol0 computes field^2 = a+b+2*sqrt(ab) and
// FFMA-accumulates e2*field^2; block reduces to double, one atomicAdd.
__global__ void __launch_bounds__(256) k3_win() {
    __shared__ unsigned int sg[8][768];           // [warp][256 pad | 256 data | 256 pad]
    __shared__ unsigned char sub[8][256];
    __shared__ float sf2[8][256];
    __shared__ double swarp[8];

    int tid = threadIdx.x;
    int w = tid >> 5;
    int lane = tid & 31;
    int pair = w >> 1;
    int pol = w & 1;
    int m = blockIdx.x;

    int hfg = g_hasfg[m];
    int afl = g_anyfalse[m];
    if (!hfg || !afl) return;                     // handled analytically in k5

    int r0g = blockIdx.y * 8 + pair * 2;
    const unsigned int* g0 = g_g + (size_t)m * HW + (size_t)r0g * Ww;

    for (int i = lane; i < 256; i += 32) {
        sg[w][i] = 0xFFFFFFFFu;
        sg[w][512 + i] = 0xFFFFFFFFu;
    }

    const uint4* a0 = (const uint4*)g0;
    const uint4* a1 = (const uint4*)(g0 + Ww);
    uint4 w00 = a0[lane * 2], w01 = a0[lane * 2 + 1];
    uint4 w10 = a1[lane * 2], w11 = a1[lane * 2 + 1];
    unsigned int r0w[8] = {w00.x, w00.y, w00.z, w00.w, w01.x, w01.y, w01.z, w01.w};
    unsigned int r1w[8] = {w10.x, w10.y, w10.z, w10.w, w11.x, w11.y, w11.z, w11.w};

    int x[8];
    int base = lane * 8;
#pragma unroll
    for (int i = 0; i < 8; i++) {
        unsigned int ga = pol ? (r0w[i] >> 16) : (r0w[i] & 0xffffu);
        unsigned int gb = pol ? (r1w[i] >> 16) : (r1w[i] & 0xffffu);
        unsigned int q0 = (ga == 0xffffu) ? 0xffffu : ga * ga;   // u16 exact (<=65025)
        unsigned int q1 = (gb == 0xffffu) ? 0xffffu : gb * gb;
        sg[w][256 + base + i] = q0 | (q1 << 16);
        x[i] = (int)min(ga, 300u);                // cap is exact (R clamps at 255)
    }

    // chamfer bound on row0 (scalar); row1 covered by ub+1 (1-Lipschitz)
    int f[8];
    int run = SCAN_INF;
#pragma unroll
    for (int i = 0; i < 8; i++) { run = min(x[i], run + 1); f[i] = run; }
    int v = run;
#pragma unroll
    for (int s = 1; s < 32; s <<= 1) {
        int o = __shfl_up_sync(0xffffffffu, v, s);
        if (lane >= s) v = min(v, o + 8 * s);
    }
    int e = __shfl_up_sync(0xffffffffu, v, 1);
    if (lane == 0) e = SCAN_INF;
#pragma unroll
    for (int i = 0; i < 8; i++) f[i] = min(f[i], e + 1 + i);

    int bw[8];
    run = SCAN_INF;
#pragma unroll
    for (int i = 7; i >= 0; i--) { run = min(x[i], run + 1); bw[i] = run; }
    int vb = run;
#pragma unroll
    for (int s = 1; s < 32; s <<= 1) {
        int o = __shfl_down_sync(0xffffffffu, vb, s);
        if (lane + s < 32) vb = min(vb, o + 8 * s);
    }
    int eb = __shfl_down_sync(0xffffffffu, vb, 1);
    if (lane == 31) eb = SCAN_INF;
#pragma unroll
    for (int i = 0; i < 8; i++) {
        int ub = min(min(f[i], bw[i]), min(eb + 8 - i, 255));
        sub[w][base + i] = (unsigned char)min(ub + 1, 255);
    }
    __syncwarp();

    const unsigned int* gp = &sg[w][256];
    float dfa[8], dfb[8];
#pragma unroll
    for (int i = 0; i < 8; i++) {
        int j = i * 32 + lane;
        unsigned int R = sub[w][j];
        R = __reduce_max_sync(0xffffffffu, R);
        unsigned int best = gp[j];
        unsigned int dd2 = 0u, inc2 = 0x00010001u;
        int nb = ((int)R + 7) >> 3;
        int dbase = 0;
        for (int bl = 0; bl < nb; bl++) {
#pragma unroll
            for (int u = 1; u <= 8; u++) {
                int d = dbase + u;                // d <= 256; index in [0,767] safe
                dd2 += inc2; inc2 += 0x00020002u;
                unsigned int ca = gp[j + d];
                unsigned int cb = gp[j - d];
                unsigned int c = __vminu2(ca, cb);
                best = __vminu2(best, __vaddus2(c, dd2));
            }
            dbase += 8;
            unsigned int hm = max(best & 0xffffu, best >> 16);
            hm = __reduce_max_sync(0xffffffffu, hm);
            if ((unsigned int)((dbase + 1) * (dbase + 1)) >= hm) break;
        }
        unsigned int h0 = best & 0xffffu, h1 = best >> 16;
        int ov = (h0 == 0xffffu) | (h1 == 0xffffu);
        if (__ballot_sync(0xffffffffu, ov)) {
            // exact u32 fallback (rare: true EDT^2 > 65535 -> R was 255)
            unsigned int b0 = BIGU, b1 = BIGU;
            for (int d = 0; d <= 255; d++) {
                unsigned int ds = (unsigned int)(d * d);
                unsigned int pa = gp[j + d], pb = gp[j - d];
                unsigned int v0 = pa & 0xffffu; v0 = (v0 == 0xffffu) ? BIGU : v0 + ds;
                unsigned int v1 = pa >> 16;     v1 = (v1 == 0xffffu) ? BIGU : v1 + ds;
                unsigned int u0 = pb & 0xffffu; u0 = (u0 == 0xffffu) ? BIGU : u0 + ds;
                unsigned int u1 = pb >> 16;     u1 = (u1 == 0xffffu) ? BIGU : u1 + ds;
                b0 = min(b0, min(v0, u0));
                b1 = min(b1, min(v1, u1));
            }
            dfa[i] = (float)((h0 == 0xffffu) ? b0 : h0);
            dfb[i] = (float)((h1 == 0xffffu) ? b1 : h1);
        } else {
            dfa[i] = (float)h0;
            dfb[i] = (float)h1;
        }
    }

    // pol exchange, field^2 = a + b + 2*sqrt(ab), accumulate e2 * field^2
    int lr = pair * 2;
    if (pol) {
#pragma unroll
        for (int i = 0; i < 8; i++) {
            sf2[lr][i * 32 + lane] = dfa[i];
            sf2[lr + 1][i * 32 + lane] = dfb[i];
        }
    }
    __syncthreads();

    float acc = 0.0f;
    if (!pol) {
        int pm = (m < HALFM) ? m : m - HALFM;
        const float* e0 = g_e2 + (size_t)pm * HW + (size_t)r0g * Ww;
#pragma unroll
        for (int i = 0; i < 8; i++) {
            int j = i * 32 + lane;
            float a = dfa[i], b = sf2[lr][j];
            float fl2 = a + b + 2.0f * __fsqrt_rn(a * b);
            acc = fmaf(e0[j], fl2, acc);
            float a2 = dfb[i], b2v = sf2[lr + 1][j];
            float fl2b = a2 + b2v + 2.0f * __fsqrt_rn(a2 * b2v);
            acc = fmaf(e0[Ww + j], fl2b, acc);
        }
    }
#pragma unroll
    for (int s = 16; s > 0; s >>= 1) acc += __shfl_down_sync(0xffffffffu, acc, s);
    if (lane == 0) swarp[w] = (double)acc;
    __syncthreads();
    if (tid == 0) {
        double tot = 0.0;
#pragma unroll
        for (int i = 0; i < 8; i++) tot += swarp[i];
        atomicAdd(&g_acc[0], tot);
    }
}

// ---------------- K5: finalize (+ analytic full/empty mask contributions) ----
__global__ void k5_final(float* __restrict__ outp) {
    __shared__ double sred[256];
    int tid = threadIdx.x;
    double extra = 0.0;
    for (int m = 0; m < NMASK; m++) {
        if (g_hasfg[m] && !g_anyfalse[m]) {       // all-true mask: field^2 == 1e12
            int pm = (m < HALFM) ? m : m - HALFM;
            const float* e = g_e2 + (size_t)pm * HW;
            float part = 0.0f;
            for (int i = tid; i < HW; i += 256) part += e[i];
            sred[tid] = (double)part;
            __syncthreads();
            for (int st = 128; st > 0; st >>= 1) {
                if (tid < st) sred[tid] += sred[tid + st];
                __syncthreads();
            }
            if (tid == 0) extra += 1e12 * sred[0];
            __syncthreads();
        }
    }
    if (tid == 0) {
        double S = g_acc[0] + extra;
        double CE = g_acc[1];
        double N = (double)Bz * (double)HW;
        outp[0] = (float)(S / N / (double)Cz / (double)Bz / 3.0 - CE / N);
    }
}

// ---------------- launch -----------------------------------------------------
extern "C" void kernel_launch(void* const* d_in, const int* in_sizes, int n_in,
                              void* d_out, int out_size) {
    const float* pred = (const float*)d_in[0];
    const void*  tgt  = d_in[1];
    float* out = (float*)d_out;

    k0_init<<<1, 128>>>((const unsigned int*)tgt);
    k1_masks<<<(Bz * HW) / 256, 256>>>(pred, tgt);
    k2_cols<<<dim3(NMASK, 4), 256>>>();
    k3_win<<<dim3(NMASK, Hh / 8), 256>>>();
    k5_final<<<1, 256>>>(out);
    (void)in_sizes; (void)n_in; (void)out_size;
}